// round 17
// baseline (speedup 1.0000x reference)
#include <cuda_runtime.h>

#define BATCH 16
#define BPC   8              // batches per chunk (2 chunks, 2 streams)
#define NCH   128
#define NC2   (NCH / 2)
#define NC4   (NCH / 4)
#define TLEN  8192
#define N1    4103
#define N2    2059
#define N3    1037

// ---- scratch (static device arrays; no allocation) --------------------------
__device__ __align__(256) float g_lo1[BATCH * N1 * NCH];
__device__ __align__(256) float g_hi1[BATCH * N1 * NCH];
__device__ __align__(256) float g_lo2[BATCH * N2 * NCH];
__device__ __align__(256) float g_hi2[BATCH * N2 * NCH];
__device__ __align__(256) float g_lo3[BATCH * N3 * NCH];
__device__ __align__(256) float g_hi3[BATCH * N3 * NCH];
__device__ __align__(256) float g_thr[BATCH * NCH];

// ---- sym8 filters (compile-time literals -> imm-form FFMA) ------------------
#define FILT_RL {  0.0018899503327594609f, -0.0003029205147241331f, -0.01495225833704823f,   \
                   0.003808752013890615f,   0.049137179673607506f,  -0.027219029917056003f,  \
                  -0.05194583810770904f,    0.36444189483533895f,    0.7771857517005235f,    \
                   0.4813596512583722f,    -0.061273359067658524f,  -0.1432942383508097f,    \
                   0.007607487324917605f,   0.03169508781149298f,   -0.0005421323317911481f, \
                  -0.0033824159510061256f }
#define FILT_RH { -0.0033824159510061256f,  0.0005421323317911481f,  0.03169508781149298f,   \
                  -0.007607487324917605f,  -0.1432942383508097f,     0.061273359067658524f,  \
                   0.4813596512583722f,    -0.7771857517005235f,     0.36444189483533895f,   \
                   0.05194583810770904f,   -0.027219029917056003f,  -0.049137179673607506f,  \
                   0.003808752013890615f,   0.01495225833704823f,   -0.0003029205147241331f, \
                  -0.0018899503327594609f }
#define FILT_DLO { -0.0033824159510061256f, -0.0005421323317911481f,  0.03169508781149298f,  \
                    0.007607487324917605f,  -0.1432942383508097f,    -0.061273359067658524f, \
                    0.4813596512583722f,     0.7771857517005235f,     0.36444189483533895f,  \
                   -0.05194583810770904f,   -0.027219029917056003f,   0.049137179673607506f, \
                    0.003808752013890615f,  -0.01495225833704823f,   -0.0003029205147241331f,\
                    0.0018899503327594609f }
#define FILT_DHI { -0.0018899503327594609f, -0.0003029205147241331f,  0.01495225833704823f,  \
                    0.003808752013890615f,  -0.049137179673607506f,  -0.027219029917056003f, \
                    0.05194583810770904f,    0.36444189483533895f,   -0.7771857517005235f,   \
                    0.4813596512583722f,     0.061273359067658524f,  -0.1432942383508097f,   \
                   -0.007607487324917605f,   0.03169508781149298f,    0.0005421323317911481f,\
                   -0.0033824159510061256f }

// 0.85 / 0.6745 * sqrt(2*log(8192))
#define THRSCALE ((float)(0.85 * 4.2452122112874176 / 0.6745))

#define WLO   0.55f
#define WHI   0.80f
#define MBINS 128
#define MCAP  32
#define KRANK 2051

#define PF 8
#define PJ 8
#define FTILE 32            // output positions per CTA (4 warps x PF)
#define FROWS (2 * FTILE + 14)   // 78 input rows for fwd tile
#define JROWS (FTILE + 7)        // 39 input rows (each of lo,hi) for inv tile

// ---- forward analysis: smem-staged tile, stride-2 16-tap --------------------
__global__ __launch_bounds__(256) void fwd_kernel(const float* __restrict__ x0,
                                                  int level, int b0) {
    const float* __restrict__ in;
    float* __restrict__ lo;
    float* __restrict__ hi;
    int nin, nout;
    if (level == 1)      { in = x0;    lo = g_lo1; hi = g_hi1; nin = TLEN; nout = N1; }
    else if (level == 2) { in = g_lo1; lo = g_lo2; hi = g_hi2; nin = N1;   nout = N2; }
    else                 { in = g_lo2; lo = g_lo3; hi = g_hi3; nin = N2;   nout = N3; }

    const int b   = b0 + blockIdx.y;
    const int nn  = threadIdx.x;          // channel pair 0..63
    const int ty  = threadIdx.y;          // 0..3
    const int tid = ty * 64 + nn;
    const int P0  = blockIdx.x * FTILE;

    const float RL[16] = FILT_RL;
    const float RH[16] = FILT_RH;

    __shared__ __align__(16) float2 s_in[FROWS][NC2];   // 39936 B

    const bool interior = (P0 >= 7) && (2 * P0 + FROWS - 1 < nin) && (P0 + FTILE <= nout);

    if (interior) {
        // ---- stage input tile: rows [2P0-14, 2P0+64), dense float4 streaming
        const float4* __restrict__ src4 = reinterpret_cast<const float4*>(in)
                                          + (size_t)(b * nin + 2 * P0 - 14) * NC4;
        const int r0 = tid >> 5;          // 0..7
        const int c  = tid & 31;          // 0..31 float4 columns
        for (int rr = r0; rr < FROWS; rr += 8)
            *reinterpret_cast<float4*>(&s_in[rr][c * 2]) = src4[(size_t)rr * NC4 + c];
        __syncthreads();

        // ---- compute PF outputs with a rolling 16-wide register window
        const int o0 = ty * PF;           // local output base (input row base 2*o0)
        float2 w[16];
#pragma unroll
        for (int k = 0; k < 16; ++k) w[k] = s_in[2 * o0 + k][nn];

        float2* __restrict__ lop = reinterpret_cast<float2*>(lo)
                                   + (size_t)(b * nout + P0 + o0) * NC2 + nn;
        float2* __restrict__ hip = reinterpret_cast<float2*>(hi)
                                   + (size_t)(b * nout + P0 + o0) * NC2 + nn;
#pragma unroll
        for (int e = 0; e < PF; ++e) {
            float2 alo = {0.f, 0.f}, ahi = {0.f, 0.f};
#pragma unroll
            for (int k = 0; k < 16; ++k) {
                const float2 v = w[k];
                alo.x += v.x * RL[k];  alo.y += v.y * RL[k];
                ahi.x += v.x * RH[k];  ahi.y += v.y * RH[k];
            }
            lop[(size_t)e * NC2] = alo;
            hip[(size_t)e * NC2] = ahi;
            if (e < PF - 1) {
#pragma unroll
                for (int k = 0; k < 14; ++k) w[k] = w[k + 2];
                w[14] = s_in[2 * o0 + 2 * e + 16][nn];
                w[15] = s_in[2 * o0 + 2 * e + 17][nn];
            }
        }
    } else {
        // ---- boundary: register-light per-tap path with symmetric reflection
        const float2* __restrict__ inb = reinterpret_cast<const float2*>(in)
                                         + (size_t)(b * nin) * NC2 + nn;
        const int p0t = P0 + ty * PF;
        for (int e = 0; e < PF; ++e) {
            const int p = p0t + e;
            if (p < nout) {
                float2 alo = {0.f, 0.f}, ahi = {0.f, 0.f};
#pragma unroll
                for (int k = 0; k < 16; ++k) {
                    int i = 2 * p - 14 + k;
                    if (i < 0)    i = -1 - i;
                    if (i >= nin) i = 2 * nin - 1 - i;
                    const float2 v = inb[(size_t)i * NC2];
                    alo.x += v.x * RL[k];  alo.y += v.y * RL[k];
                    ahi.x += v.x * RH[k];  ahi.y += v.y * RH[k];
                }
                reinterpret_cast<float2*>(lo)[(size_t)(b * nout + p) * NC2 + nn] = alo;
                reinterpret_cast<float2*>(hi)[(size_t)(b * nout + p) * NC2 + nn] = ahi;
            }
        }
    }
}

// ---- median of |cd1|: SINGLE global pass, smem candidate pool ---------------
#define CPC   8
#define HPAD  9
#define WCAP  1024
__global__ __launch_bounds__(1024) void med_kernel(int b0) {
    __shared__ unsigned int s_wind[CPC * WCAP];
    __shared__ unsigned int s_hist[MBINS * HPAD];
    __shared__ unsigned int s_below[CPC];
    __shared__ unsigned int s_wcnt[CPC];
    __shared__ unsigned int s_cand[MCAP * CPC];
    __shared__ unsigned int s_cnt[CPC];
    __shared__ int s_tbin[CPC];
    __shared__ int s_krem[CPC];
    __shared__ unsigned int s_fb;
    __shared__ int s_red;

    const int tid   = threadIdx.x;
    const int lane  = tid & 31;
    const int ch    = tid & (CPC - 1);
    const int slice = tid >> 3;
    const int b     = b0 + blockIdx.y;
    const int n0    = blockIdx.x * CPC;
    const float* __restrict__ base = g_hi1 + (size_t)(b * N1) * NCH + n0 + ch;

    for (int i = tid; i < MBINS * HPAD; i += 1024) s_hist[i] = 0u;
    if (tid < CPC) { s_below[tid] = 0u; s_wcnt[tid] = 0u; s_cnt[tid] = 0u; }
    if (tid == 0) s_fb = 0u;
    __syncthreads();

    int below = 0;
#pragma unroll 1
    for (int it = 0; it < 4; ++it) {
        float v[8];
#pragma unroll
        for (int q = 0; q < 8; ++q) {
            const int p = slice + 128 * (it * 8 + q);
            v[q] = fabsf(__ldg(base + (size_t)p * NCH));
        }
#pragma unroll
        for (int q = 0; q < 8; ++q) {
            below += (v[q] < WLO) ? 1 : 0;
            if (v[q] >= WLO && v[q] < WHI) {
                const unsigned int idx = atomicAdd(&s_wcnt[ch], 1u);
                if (idx < WCAP) s_wind[ch + CPC * idx] = __float_as_uint(v[q]);
            }
        }
    }
    {
        const int p = slice + 4096;
        if (p < N1) {
            const float v = fabsf(__ldg(base + (size_t)p * NCH));
            below += (v < WLO) ? 1 : 0;
            if (v >= WLO && v < WHI) {
                const unsigned int idx = atomicAdd(&s_wcnt[ch], 1u);
                if (idx < WCAP) s_wind[ch + CPC * idx] = __float_as_uint(v);
            }
        }
    }
    below += __shfl_down_sync(0xffffffffu, below, 16);
    below += __shfl_down_sync(0xffffffffu, below, 8);
    if (lane < CPC) atomicAdd(&s_below[lane], (unsigned int)below);
    __syncthreads();

    if (tid < CPC && s_wcnt[tid] > WCAP) atomicOr(&s_fb, 1u << tid);
    __syncthreads();

    {
        const int wc = (int)s_wcnt[ch] < WCAP ? (int)s_wcnt[ch] : WCAP;
        for (int i = slice; i < wc; i += 128) {
            const float v = __uint_as_float(s_wind[ch + CPC * i]);
            int bin = (int)((v - WLO) * 512.0f);
            bin = bin > (MBINS - 1) ? (MBINS - 1) : bin;
            atomicAdd(&s_hist[bin * HPAD + ch], 1u);
        }
    }
    __syncthreads();

    if (tid < CPC) {
        int rr = KRANK - (int)s_below[tid];
        int t = -1;
        if (rr >= 0) {
            for (int bn = 0; bn < MBINS; ++bn) {
                const int c = (int)s_hist[bn * HPAD + tid];
                if (rr < c) { t = bn; break; }
                rr -= c;
            }
        }
        s_tbin[tid] = t;
        s_krem[tid] = rr;
        if (t < 0) atomicOr(&s_fb, 1u << tid);
    }
    __syncthreads();

    {
        const int tb = s_tbin[ch];
        const int wc = (int)s_wcnt[ch] < WCAP ? (int)s_wcnt[ch] : WCAP;
        for (int i = slice; i < wc; i += 128) {
            const unsigned int bits = s_wind[ch + CPC * i];
            const float v = __uint_as_float(bits);
            int bin = (int)((v - WLO) * 512.0f);
            bin = bin > (MBINS - 1) ? (MBINS - 1) : bin;
            if (bin == tb) {
                const unsigned int idx = atomicAdd(&s_cnt[ch], 1u);
                if (idx < MCAP) s_cand[idx * CPC + ch] = bits;
            }
        }
    }
    __syncthreads();

    if (tid < CPC && s_cnt[tid] > MCAP) atomicOr(&s_fb, 1u << tid);
    __syncthreads();
    const unsigned int fb = s_fb;

    if (tid < CPC && !((fb >> tid) & 1u)) {
        const int c = (int)s_cnt[tid];
        const int k = s_krem[tid];
        unsigned int res = 0u;
        for (int i = 0; i < c; ++i) {
            const unsigned int x = s_cand[i * CPC + tid];
            int lt = 0, le = 0;
            for (int jj = 0; jj < c; ++jj) {
                const unsigned int y = s_cand[jj * CPC + tid];
                lt += (y < x);
                le += (y <= x);
            }
            if (lt <= k && k < le) res = x;
        }
        g_thr[b * NCH + n0 + tid] = __uint_as_float(res) * THRSCALE;
    }
    __syncthreads();

    if (fb) {
        for (int c2 = 0; c2 < CPC; ++c2) {
            if (!((fb >> c2) & 1u)) continue;
            const float* __restrict__ bp = g_hi1 + (size_t)(b * N1) * NCH + n0 + c2;
            unsigned int prefix = 0u;
            int kk = KRANK;
            for (int bit = 31; bit >= 0; --bit) {
                if (tid == 0) s_red = 0;
                __syncthreads();
                const unsigned int hi = prefix >> bit;
                int local = 0;
                for (int p = tid; p < N1; p += 1024) {
                    const unsigned int e = __float_as_uint(fabsf(bp[(size_t)p * NCH]));
                    if ((e >> bit) == hi) local++;
                }
                atomicAdd(&s_red, local);
                __syncthreads();
                const int c0 = s_red;
                if (kk >= c0) { kk -= c0; prefix |= (1u << bit); }
                __syncthreads();
            }
            if (tid == 0) g_thr[b * NCH + n0 + c2] = __uint_as_float(prefix) * THRSCALE;
        }
    }
}

// ---- inverse synthesis: smem-staged tile, threshold fused -------------------
__global__ __launch_bounds__(256) void inv_kernel(float* __restrict__ dout,
                                                  int level, int b0) {
    const float* __restrict__ lo;
    const float* __restrict__ hi;
    float* __restrict__ out;
    int n, nout;
    if (level == 3)      { lo = g_lo3; hi = g_hi3; out = g_lo2; n = N3; nout = N2;   }
    else if (level == 2) { lo = g_lo2; hi = g_hi2; out = g_lo1; n = N2; nout = N1;   }
    else                 { lo = g_lo1; hi = g_hi1; out = dout;  n = N1; nout = TLEN; }

    const int b   = b0 + blockIdx.y;
    const int nn  = threadIdx.x;
    const int ty  = threadIdx.y;
    const int tid = ty * 64 + nn;
    const int J0  = blockIdx.x * FTILE;

    const float DLO[16] = FILT_DLO;
    const float DHI[16] = FILT_DHI;
    const float2 thr = reinterpret_cast<const float2*>(g_thr)[b * NC2 + nn];

    __shared__ __align__(16) float2 s_lo[JROWS][NC2];   // 19968 B
    __shared__ __align__(16) float2 s_hi[JROWS][NC2];   // 19968 B

    float2* __restrict__ ob = reinterpret_cast<float2*>(out)
                              + (size_t)(b * nout) * NC2 + nn;

    const bool interior = (J0 + JROWS - 1 < n) && (2 * (J0 + FTILE) <= nout);

    if (interior) {
        // ---- stage lo/hi tiles: rows [J0, J0+39), dense float4 streaming
        const float4* __restrict__ lq4 = reinterpret_cast<const float4*>(lo)
                                         + (size_t)(b * n + J0) * NC4;
        const float4* __restrict__ hq4 = reinterpret_cast<const float4*>(hi)
                                         + (size_t)(b * n + J0) * NC4;
        const int r0 = tid >> 5;
        const int c  = tid & 31;
        for (int rr = r0; rr < JROWS; rr += 8) {
            *reinterpret_cast<float4*>(&s_lo[rr][c * 2]) = lq4[(size_t)rr * NC4 + c];
            *reinterpret_cast<float4*>(&s_hi[rr][c * 2]) = hq4[(size_t)rr * NC4 + c];
        }
        __syncthreads();

        // ---- compute with rolling 8-wide windows, threshold at insert
        const int o0 = ty * PJ;           // local j base
        float2 wl[8], wh[8];
#pragma unroll
        for (int d = 0; d < 8; ++d) {
            wl[d] = s_lo[o0 + d][nn];
            const float2 h = s_hi[o0 + d][nn];
            const float ax = fabsf(h.x) - thr.x;
            const float ay = fabsf(h.y) - thr.y;
            wh[d].x = (ax > 0.f) ? copysignf(ax, h.x) : 0.f;
            wh[d].y = (ay > 0.f) ? copysignf(ay, h.y) : 0.f;
        }
        float2* __restrict__ op = ob + (size_t)(2 * (J0 + o0)) * NC2;
#pragma unroll
        for (int e = 0; e < PJ; ++e) {
            float2 a0 = {0.f, 0.f}, a1 = {0.f, 0.f};
#pragma unroll
            for (int d = 0; d < 8; ++d) {
                const float2 l = wl[d], h = wh[d];
                a0.x += l.x * DLO[2 * d + 1] + h.x * DHI[2 * d + 1];
                a0.y += l.y * DLO[2 * d + 1] + h.y * DHI[2 * d + 1];
                a1.x += l.x * DLO[2 * d]     + h.x * DHI[2 * d];
                a1.y += l.y * DLO[2 * d]     + h.y * DHI[2 * d];
            }
            op[(size_t)(2 * e) * NC2]     = a0;
            op[(size_t)(2 * e + 1) * NC2] = a1;
            if (e < PJ - 1) {
#pragma unroll
                for (int d = 0; d < 7; ++d) { wl[d] = wl[d + 1]; wh[d] = wh[d + 1]; }
                wl[7] = s_lo[o0 + e + 8][nn];
                const float2 h = s_hi[o0 + e + 8][nn];
                const float ax = fabsf(h.x) - thr.x;
                const float ay = fabsf(h.y) - thr.y;
                wh[7].x = (ax > 0.f) ? copysignf(ax, h.x) : 0.f;
                wh[7].y = (ay > 0.f) ? copysignf(ay, h.y) : 0.f;
            }
        }
    } else {
        // ---- boundary: register-light per-tap path with clamp + store guards
        const float2* __restrict__ lob = reinterpret_cast<const float2*>(lo)
                                         + (size_t)(b * n) * NC2 + nn;
        const float2* __restrict__ hib = reinterpret_cast<const float2*>(hi)
                                         + (size_t)(b * n) * NC2 + nn;
        const int j0t = J0 + ty * PJ;
        if (2 * j0t < nout) {
            for (int e = 0; e < PJ; ++e) {
                const int m = 2 * (j0t + e);
                if (m < nout) {
                    float2 a0 = {0.f, 0.f}, a1 = {0.f, 0.f};
#pragma unroll
                    for (int d = 0; d < 8; ++d) {
                        int jj = j0t + e + d;
                        if (jj > n - 1) jj = n - 1;   // feeds only guarded-off outputs
                        const float2 l = lob[(size_t)jj * NC2];
                        const float2 h = hib[(size_t)jj * NC2];
                        float2 s;
                        const float ax = fabsf(h.x) - thr.x;
                        const float ay = fabsf(h.y) - thr.y;
                        s.x = (ax > 0.f) ? copysignf(ax, h.x) : 0.f;
                        s.y = (ay > 0.f) ? copysignf(ay, h.y) : 0.f;
                        a0.x += l.x * DLO[2 * d + 1] + s.x * DHI[2 * d + 1];
                        a0.y += l.y * DLO[2 * d + 1] + s.y * DHI[2 * d + 1];
                        a1.x += l.x * DLO[2 * d]     + s.x * DHI[2 * d];
                        a1.y += l.y * DLO[2 * d]     + s.y * DHI[2 * d];
                    }
                    ob[(size_t)m * NC2] = a0;
                    if (m + 1 < nout) ob[(size_t)(m + 1) * NC2] = a1;
                }
            }
        }
    }
}

// ---- launch: two STAGGERED batch-chunk chains on two streams ----------------
extern "C" void kernel_launch(void* const* d_in, const int* in_sizes, int n_in,
                              void* d_out, int out_size) {
    const float* x = (const float*)d_in[0];
    float* out = (float*)d_out;

    static cudaStream_t s2 = nullptr;
    static cudaEvent_t evF = nullptr, evJ = nullptr;
    if (s2 == nullptr) {
        cudaStreamCreateWithFlags(&s2, cudaStreamNonBlocking);
        cudaEventCreateWithFlags(&evF, cudaEventDisableTiming);
        cudaEventCreateWithFlags(&evJ, cudaEventDisableTiming);
    }

    const dim3 blk(64, 4);   // 64 channel pairs x 4 warps (32 positions/CTA)

    cudaEventRecord(evF, 0);
    cudaStreamWaitEvent(s2, evF, 0);

    // chunk 1 on s2: med immediately after fwd1 (stagger)
    fwd_kernel<<<dim3(129, BPC), blk, 0, s2>>>(x, 1, BPC);
    med_kernel<<<dim3(NCH / CPC, BPC), 1024, 0, s2>>>(BPC);
    fwd_kernel<<<dim3( 65, BPC), blk, 0, s2>>>(x, 2, BPC);
    fwd_kernel<<<dim3( 33, BPC), blk, 0, s2>>>(x, 3, BPC);
    inv_kernel<<<dim3( 33, BPC), blk, 0, s2>>>(out, 3, BPC);
    inv_kernel<<<dim3( 65, BPC), blk, 0, s2>>>(out, 2, BPC);
    inv_kernel<<<dim3(128, BPC), blk, 0, s2>>>(out, 1, BPC);
    cudaEventRecord(evJ, s2);

    // chunk 0 on the capture-origin stream: med after fwd3
    fwd_kernel<<<dim3(129, BPC), blk>>>(x, 1, 0);
    fwd_kernel<<<dim3( 65, BPC), blk>>>(x, 2, 0);
    fwd_kernel<<<dim3( 33, BPC), blk>>>(x, 3, 0);
    med_kernel<<<dim3(NCH / CPC, BPC), 1024>>>(0);
    inv_kernel<<<dim3( 33, BPC), blk>>>(out, 3, 0);
    inv_kernel<<<dim3( 65, BPC), blk>>>(out, 2, 0);
    inv_kernel<<<dim3(128, BPC), blk>>>(out, 1, 0);

    cudaStreamWaitEvent(0, evJ, 0);
}